// round 3
// baseline (speedup 1.0000x reference)
#include <cuda_runtime.h>
#include <math.h>

#define Lq  2048
#define Dm  1024
#define EDm 2048
#define Ns  16
#define Rr  64
#define Ee  8
#define FFm 2048
#define NP  (2*Lq)   // token-expert pairs (TOPK=2)

// ---------------- scratch (no allocations allowed) ----------------
__device__ float g_h1[Lq*Dm];
__device__ float g_xz[Lq*2*EDm];
__device__ float g_xc[Lq*EDm];
__device__ float g_xp[Lq*96];          // [dt(64) | B(16) | C(16)]
__device__ float g_delta[Lq*EDm];
__device__ float g_ys[Lq*EDm];
__device__ float g_x2[Lq*Dm];
__device__ float g_h2[Lq*Dm];
__device__ float g_hbuf[NP*FFm];
__device__ int   g_sel[NP];
__device__ float g_topw[NP];
__device__ int   g_off[Ee+1];
__device__ int   g_ptok[NP];
__device__ float g_pw[NP];

// ---------------- generic C = A @ B^T  (A:[M,K] lda, B:[N,K]) ----------------
__global__ void sgemm_abt(const float* __restrict__ A, const float* __restrict__ B,
                          float* __restrict__ C, int M, int N, int K, int lda) {
    __shared__ float As[64][17];
    __shared__ float Bs[64][17];
    int bm = blockIdx.y * 64, bn = blockIdx.x * 64;
    int tid = threadIdx.x;
    int tx = tid & 15, ty = tid >> 4;
    float acc[4][4] = {};
    for (int k0 = 0; k0 < K; k0 += 16) {
        #pragma unroll
        for (int i = 0; i < 4; i++) {
            int r = (tid >> 4) + i * 16, c = tid & 15;
            int gm = bm + r, gk = k0 + c, gn = bn + r;
            As[r][c] = (gm < M && gk < K) ? A[(size_t)gm * lda + gk] : 0.f;
            Bs[r][c] = (gn < N && gk < K) ? B[(size_t)gn * K + gk] : 0.f;
        }
        __syncthreads();
        #pragma unroll
        for (int k = 0; k < 16; k++) {
            float a[4], b[4];
            #pragma unroll
            for (int i = 0; i < 4; i++) a[i] = As[ty*4+i][k];
            #pragma unroll
            for (int j = 0; j < 4; j++) b[j] = Bs[tx*4+j][k];
            #pragma unroll
            for (int i = 0; i < 4; i++)
                #pragma unroll
                for (int j = 0; j < 4; j++) acc[i][j] += a[i] * b[j];
        }
        __syncthreads();
    }
    #pragma unroll
    for (int i = 0; i < 4; i++)
        #pragma unroll
        for (int j = 0; j < 4; j++) {
            int gm = bm + ty*4 + i, gn = bn + tx*4 + j;
            if (gm < M && gn < N) C[(size_t)gm * N + gn] = acc[i][j];
        }
}

// ---------------- rmsnorm (one block per token) ----------------
__global__ void rmsnorm_k(const float* __restrict__ x, const float* __restrict__ w,
                          float* __restrict__ o) {
    int t = blockIdx.x;
    const float* xr = x + (size_t)t * Dm;
    float s = 0.f;
    for (int i = threadIdx.x; i < Dm; i += blockDim.x) { float v = xr[i]; s += v * v; }
    __shared__ float red[32];
    for (int off = 16; off; off >>= 1) s += __shfl_xor_sync(~0u, s, off);
    if ((threadIdx.x & 31) == 0) red[threadIdx.x >> 5] = s;
    __syncthreads();
    if (threadIdx.x < 32) {
        float v = (threadIdx.x < (blockDim.x >> 5)) ? red[threadIdx.x] : 0.f;
        for (int off = 16; off; off >>= 1) v += __shfl_xor_sync(~0u, v, off);
        if (threadIdx.x == 0) red[0] = v;
    }
    __syncthreads();
    float inv = rsqrtf(red[0] / (float)Dm + 1e-6f);
    for (int i = threadIdx.x; i < Dm; i += blockDim.x)
        o[(size_t)t * Dm + i] = xr[i] * inv * w[i];
}

// ---------------- depthwise causal conv (K=4) + bias + silu ----------------
__global__ void conv_silu_k(const float* __restrict__ xz, const float* __restrict__ cw,
                            const float* __restrict__ cb, float* __restrict__ xc) {
    int idx = blockIdx.x * blockDim.x + threadIdx.x;
    if (idx >= Lq * EDm) return;
    int t = idx / EDm, e = idx % EDm;
    float acc = cb[e];
    #pragma unroll
    for (int k = 0; k < 4; k++) {
        int tt = t - 3 + k;
        if (tt >= 0) acc += cw[e * 4 + k] * xz[(size_t)tt * 2 * EDm + e];
    }
    xc[idx] = acc / (1.f + expf(-acc));
}

// ---------------- delta = softplus(raw + b_dt) ----------------
__global__ void dt_softplus_k(float* __restrict__ d, const float* __restrict__ b) {
    int idx = blockIdx.x * blockDim.x + threadIdx.x;
    if (idx >= Lq * EDm) return;
    float v = d[idx] + b[idx % EDm];
    d[idx] = (v > 20.f) ? v : log1pf(expf(v));
}

// ---------------- selective scan: warp = 2 channels x 16 states ----------------
__global__ void scan_k(const float* __restrict__ delta, const float* __restrict__ xc,
                       const float* __restrict__ xp, const float* __restrict__ A_log,
                       float* __restrict__ ys) {
    int warp = (blockIdx.x * blockDim.x + threadIdx.x) >> 5;
    int lane = threadIdx.x & 31;
    int c = lane >> 4, n = lane & 15;
    int e = warp * 2 + c;
    float A = -expf(A_log[(size_t)e * Ns + n]);
    float h = 0.f;
    for (int t = 0; t < Lq; t++) {
        float dlt = delta[(size_t)t * EDm + e];
        float xv  = xc[(size_t)t * EDm + e];
        float Bv  = xp[(size_t)t * 96 + 64 + n];
        float Cv  = xp[(size_t)t * 96 + 80 + n];
        h = expf(dlt * A) * h + dlt * Bv * xv;
        float v = h * Cv;
        v += __shfl_xor_sync(~0u, v, 1);
        v += __shfl_xor_sync(~0u, v, 2);
        v += __shfl_xor_sync(~0u, v, 4);
        v += __shfl_xor_sync(~0u, v, 8);
        if (n == 0) ys[(size_t)t * EDm + e] = v;
    }
}

// ---------------- y = (ys + D*xc) * silu(z) ----------------
__global__ void ymerge_k(float* __restrict__ ys, const float* __restrict__ xc,
                         const float* __restrict__ xz, const float* __restrict__ Dsk) {
    int idx = blockIdx.x * blockDim.x + threadIdx.x;
    if (idx >= Lq * EDm) return;
    int t = idx / EDm, e = idx % EDm;
    float z = xz[(size_t)t * 2 * EDm + EDm + e];
    float sz = z / (1.f + expf(-z));
    ys[idx] = (ys[idx] + Dsk[e] * xc[idx]) * sz;
}

// ---------------- residual add: a += b ----------------
__global__ void add_k(float* __restrict__ a, const float* __restrict__ b, int n) {
    int i = blockIdx.x * blockDim.x + threadIdx.x;
    if (i < n) a[i] += b[i];
}
__global__ void copy_k(float* __restrict__ a, const float* __restrict__ b, int n) {
    int i = blockIdx.x * blockDim.x + threadIdx.x;
    if (i < n) a[i] = b[i];
}

// ---------------- router: logits, softmax, top-2 ----------------
__global__ void router_k(const float* __restrict__ h2, const float* __restrict__ Wr,
                         float* __restrict__ out_log) {
    int t = blockIdx.x;
    int w = threadIdx.x >> 5, lane = threadIdx.x & 31;
    __shared__ float sl[Ee];
    float s = 0.f;
    for (int d = lane; d < Dm; d += 32) s += h2[(size_t)t * Dm + d] * Wr[(size_t)w * Dm + d];
    for (int off = 16; off; off >>= 1) s += __shfl_xor_sync(~0u, s, off);
    if (lane == 0) { sl[w] = s; out_log[(size_t)t * Ee + w] = s; }
    __syncthreads();
    if (threadIdx.x == 0) {
        float mx = sl[0];
        for (int e2 = 1; e2 < Ee; e2++) mx = fmaxf(mx, sl[e2]);
        float p[Ee], sum = 0.f;
        for (int e2 = 0; e2 < Ee; e2++) { p[e2] = expf(sl[e2] - mx); sum += p[e2]; }
        for (int e2 = 0; e2 < Ee; e2++) p[e2] /= sum;
        int i1 = 0;
        for (int e2 = 1; e2 < Ee; e2++) if (p[e2] > p[i1]) i1 = e2;
        int i2 = (i1 == 0) ? 1 : 0;
        for (int e2 = 0; e2 < Ee; e2++) if (e2 != i1 && p[e2] > p[i2]) i2 = e2;
        g_sel[2*t] = i1;   g_topw[2*t]   = p[i1];
        g_sel[2*t+1] = i2; g_topw[2*t+1] = p[i2];
    }
}

// ---------------- counting-sort pairs by expert (single block) ----------------
__global__ void build_pairs_k() {
    __shared__ int cnt[Ee], cur[Ee];
    if (threadIdx.x < Ee) cnt[threadIdx.x] = 0;
    __syncthreads();
    for (int p = threadIdx.x; p < NP; p += blockDim.x) atomicAdd(&cnt[g_sel[p]], 1);
    __syncthreads();
    if (threadIdx.x == 0) {
        int a = 0;
        for (int e = 0; e < Ee; e++) { g_off[e] = a; a += cnt[e]; }
        g_off[Ee] = a;
    }
    __syncthreads();
    if (threadIdx.x < Ee) cur[threadIdx.x] = g_off[threadIdx.x];
    __syncthreads();
    for (int p = threadIdx.x; p < NP; p += blockDim.x) {
        int e = g_sel[p];
        int pos = atomicAdd(&cur[e], 1);
        g_ptok[pos] = p >> 1;
        g_pw[pos]   = g_topw[p];
    }
}

// ---------------- MoE gate+up: h = silu(x@G^T) * (x@U^T) per expert segment ----
__global__ void moe_gateup_k(const float* __restrict__ h2, const float* __restrict__ gw,
                             const float* __restrict__ uw) {
    int e = blockIdx.z;
    int base = g_off[e], end = g_off[e + 1];
    int row0 = base + blockIdx.y * 64;
    if (row0 >= end) return;
    int col0 = blockIdx.x * 64;
    const float* G = gw + (size_t)e * FFm * Dm;
    const float* U = uw + (size_t)e * FFm * Dm;
    __shared__ float As[64][17], Gs[64][17], Us[64][17];
    __shared__ int toks[64];
    int tid = threadIdx.x, tx = tid & 15, ty = tid >> 4;
    if (tid < 64) { int r = row0 + tid; toks[tid] = (r < end) ? g_ptok[r] : -1; }
    __syncthreads();
    float ag[4][4] = {}, au[4][4] = {};
    for (int k0 = 0; k0 < Dm; k0 += 16) {
        #pragma unroll
        for (int i = 0; i < 4; i++) {
            int r = (tid >> 4) + i * 16, c = tid & 15;
            int tok = toks[r];
            As[r][c] = (tok >= 0) ? h2[(size_t)tok * Dm + k0 + c] : 0.f;
            Gs[r][c] = G[(size_t)(col0 + r) * Dm + k0 + c];
            Us[r][c] = U[(size_t)(col0 + r) * Dm + k0 + c];
        }
        __syncthreads();
        #pragma unroll
        for (int k = 0; k < 16; k++) {
            float a[4], bg[4], bu[4];
            #pragma unroll
            for (int i = 0; i < 4; i++) a[i] = As[ty*4+i][k];
            #pragma unroll
            for (int j = 0; j < 4; j++) { bg[j] = Gs[tx*4+j][k]; bu[j] = Us[tx*4+j][k]; }
            #pragma unroll
            for (int i = 0; i < 4; i++)
                #pragma unroll
                for (int j = 0; j < 4; j++) { ag[i][j] += a[i]*bg[j]; au[i][j] += a[i]*bu[j]; }
        }
        __syncthreads();
    }
    #pragma unroll
    for (int i = 0; i < 4; i++) {
        int row = row0 + ty*4 + i;
        if (row >= end) continue;
        #pragma unroll
        for (int j = 0; j < 4; j++) {
            float g = ag[i][j], u = au[i][j];
            g_hbuf[(size_t)row * FFm + col0 + tx*4 + j] = (g / (1.f + expf(-g))) * u;
        }
    }
}

// ---------------- MoE down: out[tok] += w * (h @ D^T) ----------------
__global__ void moe_down_k(const float* __restrict__ dw, float* __restrict__ out) {
    int e = blockIdx.z;
    int base = g_off[e], end = g_off[e + 1];
    int row0 = base + blockIdx.y * 64;
    if (row0 >= end) return;
    int col0 = blockIdx.x * 64;
    const float* Dw = dw + (size_t)e * Dm * FFm;
    __shared__ float As[64][17], Bs[64][17];
    __shared__ int toks[64];
    __shared__ float ws[64];
    int tid = threadIdx.x, tx = tid & 15, ty = tid >> 4;
    if (tid < 64) {
        int r = row0 + tid;
        toks[tid] = (r < end) ? g_ptok[r] : -1;
        ws[tid]   = (r < end) ? g_pw[r] : 0.f;
    }
    __syncthreads();
    float acc[4][4] = {};
    for (int k0 = 0; k0 < FFm; k0 += 16) {
        #pragma unroll
        for (int i = 0; i < 4; i++) {
            int r = (tid >> 4) + i * 16, c = tid & 15;
            int row = row0 + r;
            As[r][c] = (row < end) ? g_hbuf[(size_t)row * FFm + k0 + c] : 0.f;
            Bs[r][c] = Dw[(size_t)(col0 + r) * FFm + k0 + c];
        }
        __syncthreads();
        #pragma unroll
        for (int k = 0; k < 16; k++) {
            float a[4], b[4];
            #pragma unroll
            for (int i = 0; i < 4; i++) a[i] = As[ty*4+i][k];
            #pragma unroll
            for (int j = 0; j < 4; j++) b[j] = Bs[tx*4+j][k];
            #pragma unroll
            for (int i = 0; i < 4; i++)
                #pragma unroll
                for (int j = 0; j < 4; j++) acc[i][j] += a[i]*b[j];
        }
        __syncthreads();
    }
    #pragma unroll
    for (int i = 0; i < 4; i++) {
        int row = row0 + ty*4 + i;
        if (row >= end) continue;
        int tok = toks[ty*4 + i];
        float wgt = ws[ty*4 + i];
        #pragma unroll
        for (int j = 0; j < 4; j++)
            atomicAdd(&out[(size_t)tok * Dm + col0 + tx*4 + j], wgt * acc[i][j]);
    }
}

// ---------------- launch ----------------
extern "C" void kernel_launch(void* const* d_in, const int* in_sizes, int n_in,
                              void* d_out, int out_size) {
    const float* x       = (const float*)d_in[0];
    const float* rms1_w  = (const float*)d_in[1];
    const float* rms2_w  = (const float*)d_in[2];
    const float* W_in    = (const float*)d_in[3];
    const float* conv_w  = (const float*)d_in[4];
    const float* conv_b  = (const float*)d_in[5];
    const float* W_xproj = (const float*)d_in[6];
    const float* W_dt    = (const float*)d_in[7];
    const float* b_dt    = (const float*)d_in[8];
    const float* A_log   = (const float*)d_in[9];
    const float* D_skip  = (const float*)d_in[10];
    const float* W_out   = (const float*)d_in[11];
    const float* W_router= (const float*)d_in[12];
    const float* gate_w  = (const float*)d_in[13];
    const float* up_w    = (const float*)d_in[14];
    const float* down_w  = (const float*)d_in[15];
    float* out = (float*)d_out;

    float *p_h1, *p_xz, *p_xc, *p_xp, *p_delta, *p_ys, *p_x2, *p_h2;
    cudaGetSymbolAddress((void**)&p_h1, g_h1);
    cudaGetSymbolAddress((void**)&p_xz, g_xz);
    cudaGetSymbolAddress((void**)&p_xc, g_xc);
    cudaGetSymbolAddress((void**)&p_xp, g_xp);
    cudaGetSymbolAddress((void**)&p_delta, g_delta);
    cudaGetSymbolAddress((void**)&p_ys, g_ys);
    cudaGetSymbolAddress((void**)&p_x2, g_x2);
    cudaGetSymbolAddress((void**)&p_h2, g_h2);

    const int EW = 256;
    // 1) rmsnorm1
    rmsnorm_k<<<Lq, 256>>>(x, rms1_w, p_h1);
    // 2) in_proj: [2048,1024] @ [4096,1024]^T
    sgemm_abt<<<dim3(4096/64, 2048/64), 256>>>(p_h1, W_in, p_xz, Lq, 2*EDm, Dm, Dm);
    // 3) conv + silu
    conv_silu_k<<<(Lq*EDm + EW-1)/EW, EW>>>(p_xz, conv_w, conv_b, p_xc);
    // 4) x_proj: [2048,2048] @ [96,2048]^T
    sgemm_abt<<<dim3(2, 2048/64), 256>>>(p_xc, W_xproj, p_xp, Lq, 96, EDm, EDm);
    // 5) dt proj: [2048,64(lda96)] @ [2048,64]^T
    sgemm_abt<<<dim3(2048/64, 2048/64), 256>>>(p_xp, W_dt, p_delta, Lq, EDm, Rr, 96);
    dt_softplus_k<<<(Lq*EDm + EW-1)/EW, EW>>>(p_delta, b_dt);
    // 6) selective scan
    scan_k<<<128, 256>>>(p_delta, p_xc, p_xp, A_log, p_ys);
    // 7) merge + gate
    ymerge_k<<<(Lq*EDm + EW-1)/EW, EW>>>(p_ys, p_xc, p_xz, D_skip);
    // 8) out_proj: [2048,2048] @ [1024,2048]^T
    sgemm_abt<<<dim3(1024/64, 2048/64), 256>>>(p_ys, W_out, p_x2, Lq, Dm, EDm, EDm);
    // 9) residual
    add_k<<<(Lq*Dm + EW-1)/EW, EW>>>(p_x2, x, Lq*Dm);
    // 10) rmsnorm2
    rmsnorm_k<<<Lq, 256>>>(p_x2, rms2_w, p_h2);
    // 11) router (writes logits to out tail)
    router_k<<<Lq, 256>>>(p_h2, W_router, out + (size_t)Lq*Dm);
    // 12) pair sort
    build_pairs_k<<<1, 256>>>();
    // 13) seed out with residual
    copy_k<<<(Lq*Dm + EW-1)/EW, EW>>>(out, p_x2, Lq*Dm);
    // 14) MoE gate/up
    moe_gateup_k<<<dim3(FFm/64, 32, Ee), 256>>>(p_h2, gate_w, up_w);
    // 15) MoE down + weighted scatter
    moe_down_k<<<dim3(Dm/64, 32, Ee), 256>>>(down_w, out);
}

// round 4
// speedup vs baseline: 1.8518x; 1.8518x over previous
#include <cuda_runtime.h>
#include <math.h>

#define Lq  2048
#define Dm  1024
#define EDm 2048
#define Ns  16
#define Rr  64
#define Ee  8
#define FFm 2048
#define NP  (2*Lq)   // token-expert pairs (TOPK=2)

// ---------------- scratch (no allocations allowed) ----------------
__device__ float g_h1[Lq*Dm];
__device__ float g_xz[Lq*2*EDm];
__device__ float g_xc[Lq*EDm];
__device__ float g_xp[Lq*96];          // [dt(64) | B(16) | C(16)]
__device__ float g_delta[Lq*EDm];
__device__ float g_ys[Lq*EDm];
__device__ float g_x2[Lq*Dm];
__device__ float g_h2[Lq*Dm];
__device__ float g_hbuf[NP*FFm];       // gate out, then combined h
__device__ float g_ubuf[NP*FFm];       // up out
__device__ int   g_sel[NP];
__device__ float g_topw[NP];
__device__ int   g_off[Ee+1];
__device__ int   g_ptok[NP];
__device__ float g_pw[NP];

// ---------------- tf32 helpers ----------------
__device__ __forceinline__ unsigned f2tf32(float x) {
    unsigned r;
    asm("cvt.rna.tf32.f32 %0, %1;" : "=r"(r) : "f"(x));
    return r;
}
__device__ __forceinline__ void split_tf32(float x, unsigned& hi, unsigned& lo) {
    unsigned h = f2tf32(x);
    hi = h;
    lo = f2tf32(x - __uint_as_float(h));
}
__device__ __forceinline__ void mma_tf32(float c[4], const unsigned a[4], const unsigned b[2]) {
    asm volatile(
        "mma.sync.aligned.m16n8k8.row.col.f32.tf32.tf32.f32 "
        "{%0,%1,%2,%3}, {%4,%5,%6,%7}, {%8,%9}, {%0,%1,%2,%3};"
        : "+f"(c[0]), "+f"(c[1]), "+f"(c[2]), "+f"(c[3])
        : "r"(a[0]), "r"(a[1]), "r"(a[2]), "r"(a[3]), "r"(b[0]), "r"(b[1]));
}

// ============ tf32-split GEMM: C[M,N] = A[M,K]@B[N,K]^T ============
// 64x64 block tile, 128 threads (4 warps, each 32x32). Split-K via blockIdx.z.
__global__ void tmm_abt(const float* __restrict__ A, const float* __restrict__ B,
                        float* __restrict__ C, int M, int N, int Kchunk,
                        int lda, int ldb, int use_atomic) {
    __shared__ float As[64][20];
    __shared__ float Bs[64][20];
    int bm = blockIdx.y * 64, bn = blockIdx.x * 64;
    int kbase = blockIdx.z * Kchunk;
    int tid = threadIdx.x;
    int warp = tid >> 5, lane = tid & 31;
    int wm = (warp & 1) * 32, wn = (warp >> 1) * 32;
    int g = lane >> 2, tc = lane & 3;
    float c[2][4][4];
    #pragma unroll
    for (int mt = 0; mt < 2; mt++)
        #pragma unroll
        for (int nt = 0; nt < 4; nt++)
            #pragma unroll
            for (int i = 0; i < 4; i++) c[mt][nt][i] = 0.f;

    for (int k0 = kbase; k0 < kbase + Kchunk; k0 += 16) {
        #pragma unroll
        for (int j = 0; j < 2; j++) {
            int q = tid + j * 128;   // 0..255
            int r = q >> 2, c4 = q & 3;
            int gm = bm + r;
            float4 va = make_float4(0.f, 0.f, 0.f, 0.f);
            if (gm < M) va = *(const float4*)&A[(size_t)gm * lda + k0 + c4 * 4];
            *(float4*)&As[r][c4 * 4] = va;
            int gn = bn + r;
            float4 vb = make_float4(0.f, 0.f, 0.f, 0.f);
            if (gn < N) vb = *(const float4*)&B[(size_t)gn * ldb + k0 + c4 * 4];
            *(float4*)&Bs[r][c4 * 4] = vb;
        }
        __syncthreads();
        #pragma unroll
        for (int kk = 0; kk < 16; kk += 8) {
            unsigned ah[2][4], al[2][4], bh[4][2], bl[4][2];
            #pragma unroll
            for (int mt = 0; mt < 2; mt++) {
                int rb = wm + mt * 16;
                split_tf32(As[rb + g][kk + tc],       ah[mt][0], al[mt][0]);
                split_tf32(As[rb + g + 8][kk + tc],   ah[mt][1], al[mt][1]);
                split_tf32(As[rb + g][kk + tc + 4],   ah[mt][2], al[mt][2]);
                split_tf32(As[rb + g + 8][kk + tc + 4], ah[mt][3], al[mt][3]);
            }
            #pragma unroll
            for (int nt = 0; nt < 4; nt++) {
                int rb = wn + nt * 8 + g;
                split_tf32(Bs[rb][kk + tc],     bh[nt][0], bl[nt][0]);
                split_tf32(Bs[rb][kk + tc + 4], bh[nt][1], bl[nt][1]);
            }
            #pragma unroll
            for (int mt = 0; mt < 2; mt++)
                #pragma unroll
                for (int nt = 0; nt < 4; nt++) {
                    mma_tf32(c[mt][nt], ah[mt], bh[nt]);
                    mma_tf32(c[mt][nt], ah[mt], bl[nt]);
                    mma_tf32(c[mt][nt], al[mt], bh[nt]);
                }
        }
        __syncthreads();
    }
    #pragma unroll
    for (int mt = 0; mt < 2; mt++)
        #pragma unroll
        for (int nt = 0; nt < 4; nt++) {
            int r0 = bm + wm + mt * 16 + g;
            int c0 = bn + wn + nt * 8 + tc * 2;
            #pragma unroll
            for (int i = 0; i < 4; i++) {
                int gm = r0 + (i >> 1) * 8;
                int gn = c0 + (i & 1);
                if (gm < M && gn < N) {
                    if (use_atomic) atomicAdd(&C[(size_t)gm * N + gn], c[mt][nt][i]);
                    else C[(size_t)gm * N + gn] = c[mt][nt][i];
                }
            }
        }
}

// ============ MoE gate/up: Cout[pairrow, FFm] = gather(X)@W_e^T ============
__global__ void tmm_moe_proj(const float* __restrict__ X, const float* __restrict__ W,
                             float* __restrict__ Cout) {
    int e = blockIdx.z;
    int base = g_off[e], end = g_off[e + 1];
    int row0 = base + blockIdx.y * 64;
    if (row0 >= end) return;
    int col0 = blockIdx.x * 64;
    const float* Wb = W + (size_t)e * FFm * Dm;
    __shared__ float As[64][20];
    __shared__ float Bs[64][20];
    __shared__ int toks[64];
    int tid = threadIdx.x;
    int warp = tid >> 5, lane = tid & 31;
    int wm = (warp & 1) * 32, wn = (warp >> 1) * 32;
    int g = lane >> 2, tc = lane & 3;
    if (tid < 64) { int r = row0 + tid; toks[tid] = (r < end) ? g_ptok[r] : -1; }
    __syncthreads();
    float c[2][4][4];
    #pragma unroll
    for (int mt = 0; mt < 2; mt++)
        #pragma unroll
        for (int nt = 0; nt < 4; nt++)
            #pragma unroll
            for (int i = 0; i < 4; i++) c[mt][nt][i] = 0.f;

    for (int k0 = 0; k0 < Dm; k0 += 16) {
        #pragma unroll
        for (int j = 0; j < 2; j++) {
            int q = tid + j * 128;
            int r = q >> 2, c4 = q & 3;
            int tok = toks[r];
            float4 va = make_float4(0.f, 0.f, 0.f, 0.f);
            if (tok >= 0) va = *(const float4*)&X[(size_t)tok * Dm + k0 + c4 * 4];
            *(float4*)&As[r][c4 * 4] = va;
            float4 vb = *(const float4*)&Wb[(size_t)(col0 + r) * Dm + k0 + c4 * 4];
            *(float4*)&Bs[r][c4 * 4] = vb;
        }
        __syncthreads();
        #pragma unroll
        for (int kk = 0; kk < 16; kk += 8) {
            unsigned ah[2][4], al[2][4], bh[4][2], bl[4][2];
            #pragma unroll
            for (int mt = 0; mt < 2; mt++) {
                int rb = wm + mt * 16;
                split_tf32(As[rb + g][kk + tc],       ah[mt][0], al[mt][0]);
                split_tf32(As[rb + g + 8][kk + tc],   ah[mt][1], al[mt][1]);
                split_tf32(As[rb + g][kk + tc + 4],   ah[mt][2], al[mt][2]);
                split_tf32(As[rb + g + 8][kk + tc + 4], ah[mt][3], al[mt][3]);
            }
            #pragma unroll
            for (int nt = 0; nt < 4; nt++) {
                int rb = wn + nt * 8 + g;
                split_tf32(Bs[rb][kk + tc],     bh[nt][0], bl[nt][0]);
                split_tf32(Bs[rb][kk + tc + 4], bh[nt][1], bl[nt][1]);
            }
            #pragma unroll
            for (int mt = 0; mt < 2; mt++)
                #pragma unroll
                for (int nt = 0; nt < 4; nt++) {
                    mma_tf32(c[mt][nt], ah[mt], bh[nt]);
                    mma_tf32(c[mt][nt], ah[mt], bl[nt]);
                    mma_tf32(c[mt][nt], al[mt], bh[nt]);
                }
        }
        __syncthreads();
    }
    #pragma unroll
    for (int mt = 0; mt < 2; mt++)
        #pragma unroll
        for (int nt = 0; nt < 4; nt++) {
            int lr0 = wm + mt * 16 + g;
            int c0 = col0 + wn + nt * 8 + tc * 2;
            #pragma unroll
            for (int i = 0; i < 4; i++) {
                int lr = lr0 + (i >> 1) * 8;
                int row = row0 + lr;
                if (row < end)
                    Cout[(size_t)row * FFm + c0 + (i & 1)] = c[mt][nt][i];
            }
        }
}

// ============ MoE down: out[tok] += w * (Hb @ W_e^T) ============
__global__ void tmm_moe_down(const float* __restrict__ Hb, const float* __restrict__ W,
                             float* __restrict__ out) {
    int e = blockIdx.z;
    int base = g_off[e], end = g_off[e + 1];
    int row0 = base + blockIdx.y * 64;
    if (row0 >= end) return;
    int col0 = blockIdx.x * 64;
    const float* Wb = W + (size_t)e * Dm * FFm;
    __shared__ float As[64][20];
    __shared__ float Bs[64][20];
    __shared__ int toks[64];
    __shared__ float wsm[64];
    int tid = threadIdx.x;
    int warp = tid >> 5, lane = tid & 31;
    int wm = (warp & 1) * 32, wn = (warp >> 1) * 32;
    int g = lane >> 2, tc = lane & 3;
    if (tid < 64) {
        int r = row0 + tid;
        toks[tid] = (r < end) ? g_ptok[r] : -1;
        wsm[tid] = (r < end) ? g_pw[r] : 0.f;
    }
    __syncthreads();
    float c[2][4][4];
    #pragma unroll
    for (int mt = 0; mt < 2; mt++)
        #pragma unroll
        for (int nt = 0; nt < 4; nt++)
            #pragma unroll
            for (int i = 0; i < 4; i++) c[mt][nt][i] = 0.f;

    for (int k0 = 0; k0 < FFm; k0 += 16) {
        #pragma unroll
        for (int j = 0; j < 2; j++) {
            int q = tid + j * 128;
            int r = q >> 2, c4 = q & 3;
            int row = row0 + r;
            float4 va = make_float4(0.f, 0.f, 0.f, 0.f);
            if (row < end) va = *(const float4*)&Hb[(size_t)row * FFm + k0 + c4 * 4];
            *(float4*)&As[r][c4 * 4] = va;
            float4 vb = *(const float4*)&Wb[(size_t)(col0 + r) * FFm + k0 + c4 * 4];
            *(float4*)&Bs[r][c4 * 4] = vb;
        }
        __syncthreads();
        #pragma unroll
        for (int kk = 0; kk < 16; kk += 8) {
            unsigned ah[2][4], al[2][4], bh[4][2], bl[4][2];
            #pragma unroll
            for (int mt = 0; mt < 2; mt++) {
                int rb = wm + mt * 16;
                split_tf32(As[rb + g][kk + tc],       ah[mt][0], al[mt][0]);
                split_tf32(As[rb + g + 8][kk + tc],   ah[mt][1], al[mt][1]);
                split_tf32(As[rb + g][kk + tc + 4],   ah[mt][2], al[mt][2]);
                split_tf32(As[rb + g + 8][kk + tc + 4], ah[mt][3], al[mt][3]);
            }
            #pragma unroll
            for (int nt = 0; nt < 4; nt++) {
                int rb = wn + nt * 8 + g;
                split_tf32(Bs[rb][kk + tc],     bh[nt][0], bl[nt][0]);
                split_tf32(Bs[rb][kk + tc + 4], bh[nt][1], bl[nt][1]);
            }
            #pragma unroll
            for (int mt = 0; mt < 2; mt++)
                #pragma unroll
                for (int nt = 0; nt < 4; nt++) {
                    mma_tf32(c[mt][nt], ah[mt], bh[nt]);
                    mma_tf32(c[mt][nt], ah[mt], bl[nt]);
                    mma_tf32(c[mt][nt], al[mt], bh[nt]);
                }
        }
        __syncthreads();
    }
    #pragma unroll
    for (int mt = 0; mt < 2; mt++)
        #pragma unroll
        for (int nt = 0; nt < 4; nt++) {
            int lr0 = wm + mt * 16 + g;
            int c0 = col0 + wn + nt * 8 + tc * 2;
            #pragma unroll
            for (int i = 0; i < 4; i++) {
                int lr = lr0 + (i >> 1) * 8;
                int row = row0 + lr;
                if (row < end) {
                    int tok = toks[lr];
                    float wgt = wsm[lr];
                    atomicAdd(&out[(size_t)tok * Dm + c0 + (i & 1)], wgt * c[mt][nt][i]);
                }
            }
        }
}

// ---------------- rmsnorm (one block per token) ----------------
__global__ void rmsnorm_k(const float* __restrict__ x, const float* __restrict__ w,
                          float* __restrict__ o) {
    int t = blockIdx.x;
    const float* xr = x + (size_t)t * Dm;
    float s = 0.f;
    for (int i = threadIdx.x; i < Dm; i += blockDim.x) { float v = xr[i]; s += v * v; }
    __shared__ float red[32];
    for (int off = 16; off; off >>= 1) s += __shfl_xor_sync(~0u, s, off);
    if ((threadIdx.x & 31) == 0) red[threadIdx.x >> 5] = s;
    __syncthreads();
    if (threadIdx.x < 32) {
        float v = (threadIdx.x < (blockDim.x >> 5)) ? red[threadIdx.x] : 0.f;
        for (int off = 16; off; off >>= 1) v += __shfl_xor_sync(~0u, v, off);
        if (threadIdx.x == 0) red[0] = v;
    }
    __syncthreads();
    float inv = rsqrtf(red[0] / (float)Dm + 1e-6f);
    for (int i = threadIdx.x; i < Dm; i += blockDim.x)
        o[(size_t)t * Dm + i] = xr[i] * inv * w[i];
}

// ---------------- depthwise causal conv (K=4) + bias + silu ----------------
__global__ void conv_silu_k(const float* __restrict__ xz, const float* __restrict__ cw,
                            const float* __restrict__ cb, float* __restrict__ xc) {
    int idx = blockIdx.x * blockDim.x + threadIdx.x;
    if (idx >= Lq * EDm) return;
    int t = idx / EDm, e = idx % EDm;
    float acc = cb[e];
    #pragma unroll
    for (int k = 0; k < 4; k++) {
        int tt = t - 3 + k;
        if (tt >= 0) acc += cw[e * 4 + k] * xz[(size_t)tt * 2 * EDm + e];
    }
    xc[idx] = acc / (1.f + expf(-acc));
}

// ---------------- delta = softplus(raw + b_dt) ----------------
__global__ void dt_softplus_k(float* __restrict__ d, const float* __restrict__ b) {
    int idx = blockIdx.x * blockDim.x + threadIdx.x;
    if (idx >= Lq * EDm) return;
    float v = d[idx] + b[idx % EDm];
    d[idx] = (v > 20.f) ? v : log1pf(expf(v));
}

// ---------------- selective scan: warp = 2 channels x 16 states ----------------
__global__ void scan_k(const float* __restrict__ delta, const float* __restrict__ xc,
                       const float* __restrict__ xp, const float* __restrict__ A_log,
                       float* __restrict__ ys) {
    int warp = (blockIdx.x * blockDim.x + threadIdx.x) >> 5;
    int lane = threadIdx.x & 31;
    int c = lane >> 4, n = lane & 15;
    int e = warp * 2 + c;
    float A = -expf(A_log[(size_t)e * Ns + n]);
    float h = 0.f;
    for (int t = 0; t < Lq; t++) {
        float dlt = delta[(size_t)t * EDm + e];
        float xv  = xc[(size_t)t * EDm + e];
        float Bv  = xp[(size_t)t * 96 + 64 + n];
        float Cv  = xp[(size_t)t * 96 + 80 + n];
        h = expf(dlt * A) * h + dlt * Bv * xv;
        float v = h * Cv;
        v += __shfl_xor_sync(~0u, v, 1);
        v += __shfl_xor_sync(~0u, v, 2);
        v += __shfl_xor_sync(~0u, v, 4);
        v += __shfl_xor_sync(~0u, v, 8);
        if (n == 0) ys[(size_t)t * EDm + e] = v;
    }
}

// ---------------- y = (ys + D*xc) * silu(z) ----------------
__global__ void ymerge_k(float* __restrict__ ys, const float* __restrict__ xc,
                         const float* __restrict__ xz, const float* __restrict__ Dsk) {
    int idx = blockIdx.x * blockDim.x + threadIdx.x;
    if (idx >= Lq * EDm) return;
    int t = idx / EDm, e = idx % EDm;
    float z = xz[(size_t)t * 2 * EDm + EDm + e];
    float sz = z / (1.f + expf(-z));
    ys[idx] = (ys[idx] + Dsk[e] * xc[idx]) * sz;
}

// ---------------- elementwise utils ----------------
__global__ void add_k(float* __restrict__ a, const float* __restrict__ b, int n) {
    int i = blockIdx.x * blockDim.x + threadIdx.x;
    if (i < n) a[i] += b[i];
}
__global__ void copy_k(float* __restrict__ a, const float* __restrict__ b, int n) {
    int i = blockIdx.x * blockDim.x + threadIdx.x;
    if (i < n) a[i] = b[i];
}
__global__ void zero_k(float* __restrict__ a, int n) {
    int i = blockIdx.x * blockDim.x + threadIdx.x;
    if (i < n) a[i] = 0.f;
}
__global__ void glu_k(float* __restrict__ gb, const float* __restrict__ ub, int n) {
    int i = blockIdx.x * blockDim.x + threadIdx.x;
    if (i < n) {
        float gv = gb[i];
        gb[i] = (gv / (1.f + expf(-gv))) * ub[i];
    }
}

// ---------------- router: logits, softmax, top-2 (exact fp32) ----------------
__global__ void router_k(const float* __restrict__ h2, const float* __restrict__ Wr,
                         float* __restrict__ out_log) {
    int t = blockIdx.x;
    int w = threadIdx.x >> 5, lane = threadIdx.x & 31;
    __shared__ float sl[Ee];
    float s = 0.f;
    for (int d = lane; d < Dm; d += 32) s += h2[(size_t)t * Dm + d] * Wr[(size_t)w * Dm + d];
    for (int off = 16; off; off >>= 1) s += __shfl_xor_sync(~0u, s, off);
    if (lane == 0) { sl[w] = s; out_log[(size_t)t * Ee + w] = s; }
    __syncthreads();
    if (threadIdx.x == 0) {
        float mx = sl[0];
        for (int e2 = 1; e2 < Ee; e2++) mx = fmaxf(mx, sl[e2]);
        float p[Ee], sum = 0.f;
        for (int e2 = 0; e2 < Ee; e2++) { p[e2] = expf(sl[e2] - mx); sum += p[e2]; }
        for (int e2 = 0; e2 < Ee; e2++) p[e2] /= sum;
        int i1 = 0;
        for (int e2 = 1; e2 < Ee; e2++) if (p[e2] > p[i1]) i1 = e2;
        int i2 = (i1 == 0) ? 1 : 0;
        for (int e2 = 0; e2 < Ee; e2++) if (e2 != i1 && p[e2] > p[i2]) i2 = e2;
        g_sel[2*t] = i1;   g_topw[2*t]   = p[i1];
        g_sel[2*t+1] = i2; g_topw[2*t+1] = p[i2];
    }
}

// ---------------- counting-sort pairs by expert (single block) ----------------
__global__ void build_pairs_k() {
    __shared__ int cnt[Ee], cur[Ee];
    if (threadIdx.x < Ee) cnt[threadIdx.x] = 0;
    __syncthreads();
    for (int p = threadIdx.x; p < NP; p += blockDim.x) atomicAdd(&cnt[g_sel[p]], 1);
    __syncthreads();
    if (threadIdx.x == 0) {
        int a = 0;
        for (int e = 0; e < Ee; e++) { g_off[e] = a; a += cnt[e]; }
        g_off[Ee] = a;
    }
    __syncthreads();
    if (threadIdx.x < Ee) cur[threadIdx.x] = g_off[threadIdx.x];
    __syncthreads();
    for (int p = threadIdx.x; p < NP; p += blockDim.x) {
        int e = g_sel[p];
        int pos = atomicAdd(&cur[e], 1);
        g_ptok[pos] = p >> 1;
        g_pw[pos]   = g_topw[p];
    }
}

// ---------------- launch ----------------
extern "C" void kernel_launch(void* const* d_in, const int* in_sizes, int n_in,
                              void* d_out, int out_size) {
    const float* x       = (const float*)d_in[0];
    const float* rms1_w  = (const float*)d_in[1];
    const float* rms2_w  = (const float*)d_in[2];
    const float* W_in    = (const float*)d_in[3];
    const float* conv_w  = (const float*)d_in[4];
    const float* conv_b  = (const float*)d_in[5];
    const float* W_xproj = (const float*)d_in[6];
    const float* W_dt    = (const float*)d_in[7];
    const float* b_dt    = (const float*)d_in[8];
    const float* A_log   = (const float*)d_in[9];
    const float* D_skip  = (const float*)d_in[10];
    const float* W_out   = (const float*)d_in[11];
    const float* W_router= (const float*)d_in[12];
    const float* gate_w  = (const float*)d_in[13];
    const float* up_w    = (const float*)d_in[14];
    const float* down_w  = (const float*)d_in[15];
    float* out = (float*)d_out;

    float *p_h1, *p_xz, *p_xc, *p_xp, *p_delta, *p_ys, *p_x2, *p_h2, *p_hbuf, *p_ubuf;
    cudaGetSymbolAddress((void**)&p_h1, g_h1);
    cudaGetSymbolAddress((void**)&p_xz, g_xz);
    cudaGetSymbolAddress((void**)&p_xc, g_xc);
    cudaGetSymbolAddress((void**)&p_xp, g_xp);
    cudaGetSymbolAddress((void**)&p_delta, g_delta);
    cudaGetSymbolAddress((void**)&p_ys, g_ys);
    cudaGetSymbolAddress((void**)&p_x2, g_x2);
    cudaGetSymbolAddress((void**)&p_h2, g_h2);
    cudaGetSymbolAddress((void**)&p_hbuf, g_hbuf);
    cudaGetSymbolAddress((void**)&p_ubuf, g_ubuf);

    const int EW = 256;
    // 1) rmsnorm1
    rmsnorm_k<<<Lq, 256>>>(x, rms1_w, p_h1);
    // 2) in_proj: [2048,1024] @ [4096,1024]^T
    tmm_abt<<<dim3(4096/64, 2048/64, 1), 128>>>(p_h1, W_in, p_xz, Lq, 2*EDm, Dm, Dm, Dm, 0);
    // 3) conv + silu
    conv_silu_k<<<(Lq*EDm + EW-1)/EW, EW>>>(p_xz, conv_w, conv_b, p_xc);
    // 4) x_proj (split-K=8, atomic): [2048,2048] @ [96,2048]^T
    zero_k<<<(Lq*96 + EW-1)/EW, EW>>>(p_xp, Lq*96);
    tmm_abt<<<dim3(2, 2048/64, 8), 128>>>(p_xc, W_xproj, p_xp, Lq, 96, EDm/8, EDm, EDm, 1);
    // 5) dt proj: [2048,64(lda96)] @ [2048,64]^T
    tmm_abt<<<dim3(2048/64, 2048/64, 1), 128>>>(p_xp, W_dt, p_delta, Lq, EDm, Rr, 96, Rr, 0);
    dt_softplus_k<<<(Lq*EDm + EW-1)/EW, EW>>>(p_delta, b_dt);
    // 6) selective scan
    scan_k<<<128, 256>>>(p_delta, p_xc, p_xp, A_log, p_ys);
    // 7) merge + gate
    ymerge_k<<<(Lq*EDm + EW-1)/EW, EW>>>(p_ys, p_xc, p_xz, D_skip);
    // 8) out_proj: [2048,2048] @ [1024,2048]^T
    tmm_abt<<<dim3(1024/64, 2048/64, 1), 128>>>(p_ys, W_out, p_x2, Lq, Dm, EDm, EDm, EDm, 0);
    // 9) residual
    add_k<<<(Lq*Dm + EW-1)/EW, EW>>>(p_x2, x, Lq*Dm);
    // 10) rmsnorm2
    rmsnorm_k<<<Lq, 256>>>(p_x2, rms2_w, p_h2);
    // 11) router (writes logits to out tail)
    router_k<<<Lq, 256>>>(p_h2, W_router, out + (size_t)Lq*Dm);
    // 12) pair sort
    build_pairs_k<<<1, 256>>>();
    // 13) seed out with residual
    copy_k<<<(Lq*Dm + EW-1)/EW, EW>>>(out, p_x2, Lq*Dm);
    // 14) MoE gate and up projections
    tmm_moe_proj<<<dim3(FFm/64, 32, Ee), 128>>>(p_h2, gate_w, p_hbuf);
    tmm_moe_proj<<<dim3(FFm/64, 32, Ee), 128>>>(p_h2, up_w, p_ubuf);
    // 15) h = silu(g)*u  (all NP rows are populated)
    glu_k<<<(NP*FFm + EW-1)/EW, EW>>>(p_hbuf, p_ubuf, NP*FFm);
    // 16) MoE down + weighted scatter
    tmm_moe_down<<<dim3(Dm/64, 32, Ee), 128>>>(p_hbuf, down_w, out);
}